// round 2
// baseline (speedup 1.0000x reference)
#include <cuda_runtime.h>
#include <math.h>

// Problem constants
#define Bb 8
#define Ss 2048
#define Hh 1024
#define NEG (-1e12f)

constexpr int BM = 128, BN = 128, BK = 8;

// Scratch (static device memory; allocation-free per harness rules)
__device__ float g_q[(size_t)Bb * Ss * Hh];
__device__ float g_k[(size_t)Bb * Ss * Hh];
__device__ float g_v[(size_t)Bb * Ss * Hh];
__device__ float g_ctx[(size_t)Bb * Ss * Hh];

// ---------------- packed f32x2 helpers (FFMA2 path ptxas won't emit itself) ---------
__device__ __forceinline__ unsigned long long pack2(float lo, float hi) {
    unsigned long long r;
    asm("mov.b64 %0, {%1, %2};" : "=l"(r) : "r"(__float_as_uint(lo)), "r"(__float_as_uint(hi)));
    return r;
}
__device__ __forceinline__ unsigned long long rep2(float v) {
    unsigned long long r;
    asm("mov.b64 %0, {%1, %1};" : "=l"(r) : "r"(__float_as_uint(v)));
    return r;
}
__device__ __forceinline__ void fma2(unsigned long long& c, unsigned long long a, unsigned long long b) {
    asm("fma.rn.f32x2 %0, %1, %2, %0;" : "+l"(c) : "l"(a), "l"(b));
}
__device__ __forceinline__ float2 unpack2(unsigned long long v) {
    unsigned lo, hi;
    asm("mov.b64 {%0, %1}, %2;" : "=r"(lo), "=r"(hi) : "l"(v));
    return make_float2(__uint_as_float(lo), __uint_as_float(hi));
}
__device__ __forceinline__ float4 to4(unsigned long long a, unsigned long long b) {
    float2 x = unpack2(a), y = unpack2(b);
    return make_float4(x.x, x.y, y.x, y.y);
}

// ---------------- GEMM core: C[128x128] tile of A[M,K] * B ---------------------------
// BT=true : B is [N,K] row-major (x @ W^T style, and q @ k^T)
// BT=false: B is [K,N] row-major (attn @ v)
template <bool BT>
__device__ __forceinline__ void gemm_core(const float* __restrict__ A,
                                          const float* __restrict__ B,
                                          int K, int N, int bm, int bn,
                                          unsigned long long (&acc)[8][4]) {
    __shared__ float As[BK][BM];
    __shared__ float Bs[BK][BN];
    const int tid  = threadIdx.x;
    const int tx   = tid & 15;
    const int ty   = tid >> 4;
    const int lrow = tid >> 1;         // 0..127
    const int lcol = (tid & 1) * 4;    // 0 or 4
    const int nrow = tid >> 5;         // 0..7   (NN layout)
    const int ncol = (tid & 31) * 4;   // 0..124

    for (int kt = 0; kt < K; kt += BK) {
        float4 av = *(const float4*)(A + (size_t)(bm + lrow) * K + kt + lcol);
        As[lcol + 0][lrow] = av.x;
        As[lcol + 1][lrow] = av.y;
        As[lcol + 2][lrow] = av.z;
        As[lcol + 3][lrow] = av.w;
        if (BT) {
            float4 bv = *(const float4*)(B + (size_t)(bn + lrow) * K + kt + lcol);
            Bs[lcol + 0][lrow] = bv.x;
            Bs[lcol + 1][lrow] = bv.y;
            Bs[lcol + 2][lrow] = bv.z;
            Bs[lcol + 3][lrow] = bv.w;
        } else {
            float4 bv = *(const float4*)(B + (size_t)(kt + nrow) * N + bn + ncol);
            *(float4*)&Bs[nrow][ncol] = bv;
        }
        __syncthreads();
#pragma unroll
        for (int kk = 0; kk < BK; kk++) {
            float4 a0 = *(const float4*)&As[kk][ty * 4];
            float4 a1 = *(const float4*)&As[kk][ty * 4 + 64];
            float4 b0 = *(const float4*)&Bs[kk][tx * 4];
            float4 b1 = *(const float4*)&Bs[kk][tx * 4 + 64];
            unsigned long long bp0 = pack2(b0.x, b0.y);
            unsigned long long bp1 = pack2(b0.z, b0.w);
            unsigned long long bp2 = pack2(b1.x, b1.y);
            unsigned long long bp3 = pack2(b1.z, b1.w);
            float ra[8] = {a0.x, a0.y, a0.z, a0.w, a1.x, a1.y, a1.z, a1.w};
#pragma unroll
            for (int i = 0; i < 8; i++) {
                unsigned long long ar = rep2(ra[i]);
                fma2(acc[i][0], ar, bp0);
                fma2(acc[i][1], ar, bp1);
                fma2(acc[i][2], ar, bp2);
                fma2(acc[i][3], ar, bp3);
            }
        }
        __syncthreads();
    }
}

__device__ __forceinline__ int rloc(int i, int ty) {
    return (i < 4) ? (ty * 4 + i) : (64 + ty * 4 + (i - 4));
}

// ---------------- Kernels ------------------------------------------------------------

// q/k/v = x @ W^T + b  (q pre-scaled by 1/(T*sqrt(H)) = 1/32)
__global__ __launch_bounds__(256) void qkv_kernel(const float* __restrict__ x,
                                                  const float* __restrict__ Wq, const float* __restrict__ bq,
                                                  const float* __restrict__ Wk, const float* __restrict__ bk,
                                                  const float* __restrict__ Wv, const float* __restrict__ bv) {
    const int bm = blockIdx.y * BM, bn = blockIdx.x * BN;
    const float* W; const float* bias; float* out; float scale;
    if (blockIdx.z == 0)      { W = Wq; bias = bq; out = g_q; scale = 1.0f / 32.0f; }
    else if (blockIdx.z == 1) { W = Wk; bias = bk; out = g_k; scale = 1.0f; }
    else                      { W = Wv; bias = bv; out = g_v; scale = 1.0f; }

    unsigned long long acc[8][4];
#pragma unroll
    for (int i = 0; i < 8; i++)
#pragma unroll
        for (int j = 0; j < 4; j++) acc[i][j] = 0ull;

    gemm_core<true>(x, W, Hh, Hh, bm, bn, acc);

    const int tx = threadIdx.x & 15, ty = threadIdx.x >> 4;
    const int c0 = bn + tx * 4, c1 = bn + 64 + tx * 4;
    float4 bia0 = *(const float4*)(bias + c0);
    float4 bia1 = *(const float4*)(bias + c1);
#pragma unroll
    for (int i = 0; i < 8; i++) {
        int gr = bm + rloc(i, ty);
        float4 lo = to4(acc[i][0], acc[i][1]);
        float4 hi = to4(acc[i][2], acc[i][3]);
        lo.x = (lo.x + bia0.x) * scale; lo.y = (lo.y + bia0.y) * scale;
        lo.z = (lo.z + bia0.z) * scale; lo.w = (lo.w + bia0.w) * scale;
        hi.x = (hi.x + bia1.x) * scale; hi.y = (hi.y + bia1.y) * scale;
        hi.z = (hi.z + bia1.z) * scale; hi.w = (hi.w + bia1.w) * scale;
        *(float4*)(out + (size_t)gr * Hh + c0) = lo;
        *(float4*)(out + (size_t)gr * Hh + c1) = hi;
    }
}

// scores = q @ k^T (+ bias, mask)  -> written to attn region (pre-softmax)
__global__ __launch_bounds__(256) void scores_kernel(const float* __restrict__ attn_bias,
                                                     const int* __restrict__ mask,
                                                     float* __restrict__ attn) {
    const int b = blockIdx.z;
    const int bm = blockIdx.y * BM, bn = blockIdx.x * BN;
    const float* A = g_q + (size_t)b * Ss * Hh;
    const float* Bp = g_k + (size_t)b * Ss * Hh;

    unsigned long long acc[8][4];
#pragma unroll
    for (int i = 0; i < 8; i++)
#pragma unroll
        for (int j = 0; j < 4; j++) acc[i][j] = 0ull;

    gemm_core<true>(A, Bp, Hh, Hh, bm, bn, acc);

    const int tx = threadIdx.x & 15, ty = threadIdx.x >> 4;
    const int c0 = bn + tx * 4, c1 = bn + 64 + tx * 4;
#pragma unroll
    for (int i = 0; i < 8; i++) {
        int gr = bm + rloc(i, ty);
        size_t boff = ((size_t)b * Ss + gr) * Ss;
        size_t moff = (size_t)gr * Ss;
        float4 lo = to4(acc[i][0], acc[i][1]);
        float4 hi = to4(acc[i][2], acc[i][3]);
        float4 bb0 = *(const float4*)(attn_bias + boff + c0);
        float4 bb1 = *(const float4*)(attn_bias + boff + c1);
        int4 m0 = *(const int4*)(mask + moff + c0);
        int4 m1 = *(const int4*)(mask + moff + c1);
        lo.x = m0.x ? lo.x + bb0.x : NEG; lo.y = m0.y ? lo.y + bb0.y : NEG;
        lo.z = m0.z ? lo.z + bb0.z : NEG; lo.w = m0.w ? lo.w + bb0.w : NEG;
        hi.x = m1.x ? hi.x + bb1.x : NEG; hi.y = m1.y ? hi.y + bb1.y : NEG;
        hi.z = m1.z ? hi.z + bb1.z : NEG; hi.w = m1.w ? hi.w + bb1.w : NEG;
        *(float4*)(attn + boff + c0) = lo;
        *(float4*)(attn + boff + c1) = hi;
    }
}

// ---------------- reductions ----------------------------------------------------------
__device__ __forceinline__ float warpMax(float v) {
#pragma unroll
    for (int o = 16; o; o >>= 1) v = fmaxf(v, __shfl_xor_sync(0xffffffffu, v, o));
    return v;
}
__device__ __forceinline__ float warpSum(float v) {
#pragma unroll
    for (int o = 16; o; o >>= 1) v += __shfl_xor_sync(0xffffffffu, v, o);
    return v;
}
__device__ __forceinline__ float blockMax(float v) {
    __shared__ float sh[8];
    v = warpMax(v);
    if ((threadIdx.x & 31) == 0) sh[threadIdx.x >> 5] = v;
    __syncthreads();
    float r = fmaxf(fmaxf(fmaxf(sh[0], sh[1]), fmaxf(sh[2], sh[3])),
                    fmaxf(fmaxf(sh[4], sh[5]), fmaxf(sh[6], sh[7])));
    __syncthreads();
    return r;
}
__device__ __forceinline__ float blockSum(float v) {
    __shared__ float sh[8];
    v = warpSum(v);
    if ((threadIdx.x & 31) == 0) sh[threadIdx.x >> 5] = v;
    __syncthreads();
    float r = sh[0] + sh[1] + sh[2] + sh[3] + sh[4] + sh[5] + sh[6] + sh[7];
    __syncthreads();
    return r;
}

// row-wise softmax over S=2048; one block (256 thr) per row; row held in registers
__global__ __launch_bounds__(256) void softmax_kernel(float* __restrict__ attn) {
    size_t row = blockIdx.x;
    float4* p = (float4*)(attn + row * Ss);
    int tid = threadIdx.x;
    float4 v0 = p[tid];
    float4 v1 = p[tid + 256];
    float m = fmaxf(fmaxf(fmaxf(v0.x, v0.y), fmaxf(v0.z, v0.w)),
                    fmaxf(fmaxf(v1.x, v1.y), fmaxf(v1.z, v1.w)));
    m = blockMax(m);
    v0.x = __expf(v0.x - m); v0.y = __expf(v0.y - m);
    v0.z = __expf(v0.z - m); v0.w = __expf(v0.w - m);
    v1.x = __expf(v1.x - m); v1.y = __expf(v1.y - m);
    v1.z = __expf(v1.z - m); v1.w = __expf(v1.w - m);
    float s = v0.x + v0.y + v0.z + v0.w + v1.x + v1.y + v1.z + v1.w;
    s = blockSum(s);
    float inv = 1.0f / s;
    v0.x *= inv; v0.y *= inv; v0.z *= inv; v0.w *= inv;
    v1.x *= inv; v1.y *= inv; v1.z *= inv; v1.w *= inv;
    p[tid] = v0;
    p[tid + 256] = v1;
}

// ctx = attn @ v   (per batch; B is [K=S, N=H] row-major)
__global__ __launch_bounds__(256) void av_kernel(const float* __restrict__ attn) {
    const int b = blockIdx.z;
    const int bm = blockIdx.y * BM, bn = blockIdx.x * BN;
    const float* A = attn + (size_t)b * Ss * Ss;
    const float* Bp = g_v + (size_t)b * Ss * Hh;

    unsigned long long acc[8][4];
#pragma unroll
    for (int i = 0; i < 8; i++)
#pragma unroll
        for (int j = 0; j < 4; j++) acc[i][j] = 0ull;

    gemm_core<false>(A, Bp, Ss, Hh, bm, bn, acc);

    const int tx = threadIdx.x & 15, ty = threadIdx.x >> 4;
    const int c0 = bn + tx * 4, c1 = bn + 64 + tx * 4;
#pragma unroll
    for (int i = 0; i < 8; i++) {
        int gr = bm + rloc(i, ty);
        size_t off = ((size_t)b * Ss + gr) * Hh;
        *(float4*)(g_ctx + off + c0) = to4(acc[i][0], acc[i][1]);
        *(float4*)(g_ctx + off + c1) = to4(acc[i][2], acc[i][3]);
    }
}

// out = ctx @ Wa^T + ba + residual(x)
__global__ __launch_bounds__(256) void proj_kernel(const float* __restrict__ Wa,
                                                   const float* __restrict__ ba,
                                                   const float* __restrict__ x,
                                                   float* __restrict__ out) {
    const int bm = blockIdx.y * BM, bn = blockIdx.x * BN;

    unsigned long long acc[8][4];
#pragma unroll
    for (int i = 0; i < 8; i++)
#pragma unroll
        for (int j = 0; j < 4; j++) acc[i][j] = 0ull;

    gemm_core<true>(g_ctx, Wa, Hh, Hh, bm, bn, acc);

    const int tx = threadIdx.x & 15, ty = threadIdx.x >> 4;
    const int c0 = bn + tx * 4, c1 = bn + 64 + tx * 4;
    float4 bia0 = *(const float4*)(ba + c0);
    float4 bia1 = *(const float4*)(ba + c1);
#pragma unroll
    for (int i = 0; i < 8; i++) {
        int gr = bm + rloc(i, ty);
        size_t off = (size_t)gr * Hh;
        float4 lo = to4(acc[i][0], acc[i][1]);
        float4 hi = to4(acc[i][2], acc[i][3]);
        float4 r0 = *(const float4*)(x + off + c0);
        float4 r1 = *(const float4*)(x + off + c1);
        lo.x += bia0.x + r0.x; lo.y += bia0.y + r0.y;
        lo.z += bia0.z + r0.z; lo.w += bia0.w + r0.w;
        hi.x += bia1.x + r1.x; hi.y += bia1.y + r1.y;
        hi.z += bia1.z + r1.z; hi.w += bia1.w + r1.w;
        *(float4*)(out + off + c0) = lo;
        *(float4*)(out + off + c1) = hi;
    }
}

// in-place LayerNorm over last dim (H=1024), biased variance, eps=1e-6
__global__ __launch_bounds__(256) void ln_kernel(float* __restrict__ out,
                                                 const float* __restrict__ gamma,
                                                 const float* __restrict__ beta) {
    size_t row = blockIdx.x;
    float4* p = (float4*)(out + row * Hh);
    int tid = threadIdx.x;
    float4 v = p[tid];
    float s = v.x + v.y + v.z + v.w;
    s = blockSum(s);
    float mu = s * (1.0f / Hh);
    float dx = v.x - mu, dy = v.y - mu, dz = v.z - mu, dw = v.w - mu;
    float sq = dx * dx + dy * dy + dz * dz + dw * dw;
    sq = blockSum(sq);
    float rstd = rsqrtf(sq * (1.0f / Hh) + 1e-6f);
    float4 g = ((const float4*)gamma)[tid];
    float4 bt = ((const float4*)beta)[tid];
    v.x = dx * rstd * g.x + bt.x;
    v.y = dy * rstd * g.y + bt.y;
    v.z = dz * rstd * g.z + bt.z;
    v.w = dw * rstd * g.w + bt.w;
    p[tid] = v;
}

// ---------------- launch --------------------------------------------------------------
extern "C" void kernel_launch(void* const* d_in, const int* in_sizes, int n_in,
                              void* d_out, int out_size) {
    const float* x         = (const float*)d_in[0];
    const int*   mask      = (const int*)  d_in[1];
    const float* attn_bias = (const float*)d_in[2];
    const float* Wq = (const float*)d_in[3];  const float* bq = (const float*)d_in[4];
    const float* Wk = (const float*)d_in[5];  const float* bk = (const float*)d_in[6];
    const float* Wv = (const float*)d_in[7];  const float* bv = (const float*)d_in[8];
    const float* Wa = (const float*)d_in[9];  const float* ba = (const float*)d_in[10];
    const float* gamma = (const float*)d_in[11];
    const float* beta  = (const float*)d_in[12];

    float* out  = (float*)d_out;
    float* attn = out + (size_t)Bb * Ss * Hh;  // tuple (out, attn) flattened

    dim3 blk(256);
    qkv_kernel<<<dim3(Hh / BN, (Bb * Ss) / BM, 3), blk>>>(x, Wq, bq, Wk, bk, Wv, bv);
    scores_kernel<<<dim3(Ss / BN, Ss / BM, Bb), blk>>>(attn_bias, mask, attn);
    softmax_kernel<<<Bb * Ss, blk>>>(attn);
    av_kernel<<<dim3(Hh / BN, Ss / BM, Bb), blk>>>(attn);
    proj_kernel<<<dim3(Hh / BN, (Bb * Ss) / BM, 1), blk>>>(Wa, ba, x, out);
    ln_kernel<<<Bb * Ss, blk>>>(out, gamma, beta);
}

// round 4
// speedup vs baseline: 2.2466x; 2.2466x over previous
#include <cuda_runtime.h>
#include <cstdint>
#include <math.h>

#define Bb 8
#define Ss 2048
#define Hh 1024
#define NEGV (-1e12f)

// ---------------- mma.sync tf32 GEMM configuration -----------------------------------
constexpr int BM = 128, BN = 256, BKT = 32;        // CTA tile
constexpr int ROWB = 36 * 4;                       // smem row pitch: 32 floats + 4 pad = 144B
constexpr int ABYTES = BM * ROWB;                  // 18432
constexpr int BBYTES = BN * ROWB;                  // 36864
constexpr int STAGE  = ABYTES + BBYTES;            // 55296
constexpr int NSTG   = 3;
constexpr int DYN_SMEM = NSTG * STAGE;             // 165888

// ---------------- scratch (static device memory) -------------------------------------
__device__ float g_xr [(size_t)Bb * Ss * Hh];
__device__ float g_q  [(size_t)Bb * Ss * Hh];
__device__ float g_k  [(size_t)Bb * Ss * Hh];
__device__ float g_v  [(size_t)Bb * Ss * Hh];
__device__ float g_vt [(size_t)Bb * Ss * Hh];
__device__ float g_ctx[(size_t)Bb * Ss * Hh];
__device__ float g_wq[Hh * Hh], g_wk[Hh * Hh], g_wv[Hh * Hh], g_wa[Hh * Hh];

// ---------------- helpers --------------------------------------------------------------
__device__ __forceinline__ uint32_t smem_u32(const void* p) {
    uint32_t a;
    asm("{ .reg .u64 t; cvta.to.shared.u64 t, %1; cvt.u32.u64 %0, t; }" : "=r"(a) : "l"(p));
    return a;
}
__device__ __forceinline__ float tf32r(float x) {
    uint32_t u;
    asm("cvt.rna.tf32.f32 %0, %1;" : "=r"(u) : "f"(x));
    return __uint_as_float(u);
}
__device__ __forceinline__ void cpa(uint32_t dst, const float* src) {
    asm volatile("cp.async.cg.shared.global [%0], [%1], 16;" :: "r"(dst), "l"(src));
}
__device__ __forceinline__ void cpa_commit() { asm volatile("cp.async.commit_group;"); }
template <int N>
__device__ __forceinline__ void cpa_wait() { asm volatile("cp.async.wait_group %0;" :: "n"(N)); }

__device__ __forceinline__ void mma8(float d[4], const uint32_t a[4], const uint32_t b[2]) {
    asm volatile(
        "mma.sync.aligned.m16n8k8.row.col.f32.tf32.tf32.f32 "
        "{%0,%1,%2,%3}, {%4,%5,%6,%7}, {%8,%9}, {%0,%1,%2,%3};"
        : "+f"(d[0]), "+f"(d[1]), "+f"(d[2]), "+f"(d[3])
        : "r"(a[0]), "r"(a[1]), "r"(a[2]), "r"(a[3]), "r"(b[0]), "r"(b[1]));
}

// ---------------- GEMM mainloop: acc[4][8][4] = A[bm:bm+128] * B[bn:bn+256]^T ---------
// A: [M,K] row-major, B: [N,K] row-major (i.e. computes A @ B^T)
__device__ __forceinline__ void gemm_loop(const float* __restrict__ A,
                                          const float* __restrict__ B,
                                          int K, int lda, int ldb, int bm, int bn,
                                          float acc[4][8][4]) {
    extern __shared__ __align__(16) char dsm[];
    const int tid = threadIdx.x;
    const int wid = tid >> 5, lane = tid & 31;
    const int gid = lane >> 2, tig = lane & 3;
    const int wm = (wid & 1) * 64, wn = (wid >> 1) * 64;
    const int NK = K / BKT;

#pragma unroll
    for (int mi = 0; mi < 4; mi++)
#pragma unroll
        for (int ni = 0; ni < 8; ni++)
#pragma unroll
            for (int j = 0; j < 4; j++) acc[mi][ni][j] = 0.0f;

    const int ar = tid >> 1, ac = (tid & 1) * 16;   // A: row ar, float offset ac
    const uint32_t sbase = smem_u32(dsm);

    auto load_tile = [&](int s, int kt) {
        uint32_t sA = sbase + s * STAGE;
        uint32_t sB = sA + ABYTES;
        const float* asrc = A + (size_t)(bm + ar) * lda + kt * BKT + ac;
        uint32_t ad = sA + ar * ROWB + ac * 4;
#pragma unroll
        for (int c = 0; c < 4; c++) cpa(ad + c * 16, asrc + c * 4);
        const float* bsrc = B + (size_t)(bn + tid) * ldb + kt * BKT;
        uint32_t bd = sB + tid * ROWB;
#pragma unroll
        for (int c = 0; c < 8; c++) cpa(bd + c * 16, bsrc + c * 4);
    };

    load_tile(0, 0); cpa_commit();
    load_tile(1, 1); cpa_commit();

    for (int kt = 0; kt < NK; kt++) {
        const int s = kt % NSTG;
        if (kt + 1 < NK) cpa_wait<1>(); else cpa_wait<0>();
        __syncthreads();
        if (kt + 2 < NK) { load_tile((kt + 2) % NSTG, kt + 2); cpa_commit(); }

        const float* As = (const float*)(dsm + s * STAGE);
        const float* Bs = (const float*)(dsm + s * STAGE + ABYTES);
#pragma unroll
        for (int kk = 0; kk < 4; kk++) {
            uint32_t a[4][4], b[8][2];
#pragma unroll
            for (int mi = 0; mi < 4; mi++) {
                const float* p0 = As + (wm + mi * 16 + gid) * 36 + kk * 8 + tig;
                const float* p1 = p0 + 8 * 36;
                a[mi][0] = __float_as_uint(p0[0]);
                a[mi][1] = __float_as_uint(p1[0]);
                a[mi][2] = __float_as_uint(p0[4]);
                a[mi][3] = __float_as_uint(p1[4]);
            }
#pragma unroll
            for (int ni = 0; ni < 8; ni++) {
                const float* p = Bs + (wn + ni * 8 + gid) * 36 + kk * 8 + tig;
                b[ni][0] = __float_as_uint(p[0]);
                b[ni][1] = __float_as_uint(p[4]);
            }
#pragma unroll
            for (int mi = 0; mi < 4; mi++)
#pragma unroll
                for (int ni = 0; ni < 8; ni++)
                    mma8(acc[mi][ni], a[mi], b[ni]);
        }
        // next-iteration top barrier provides the reuse fence
    }
}

// fragment -> global coordinates helper values
#define EPI_SETUP()                                        \
    const int tid = threadIdx.x;                           \
    const int wid = tid >> 5, lane = tid & 31;             \
    const int gid = lane >> 2, tig = lane & 3;             \
    const int wm = (wid & 1) * 64, wn = (wid >> 1) * 64;   \
    const int bm = blockIdx.y * BM, bn = blockIdx.x * BN;  \
    (void)bm; (void)bn;

// ---------------- GEMM kernels ---------------------------------------------------------

// q/k/v = round_tf32((x_r @ W^T + b) * scale);  q folds 1/(T*sqrt(H)) = 1/32
__global__ __launch_bounds__(256, 1) void qkv_tc(const float* __restrict__ bq,
                                                 const float* __restrict__ bk,
                                                 const float* __restrict__ bv) {
    EPI_SETUP();
    const float* W; const float* bias; float* out; float scale;
    if (blockIdx.z == 0)      { W = g_wq; bias = bq; out = g_q; scale = 1.0f / 32.0f; }
    else if (blockIdx.z == 1) { W = g_wk; bias = bk; out = g_k; scale = 1.0f; }
    else                      { W = g_wv; bias = bv; out = g_v; scale = 1.0f; }

    float acc[4][8][4];
    gemm_loop(g_xr, W, Hh, Hh, Hh, bm, bn, acc);

#pragma unroll
    for (int mi = 0; mi < 4; mi++) {
        const int r0 = bm + wm + mi * 16 + gid;
        float* o0 = out + (size_t)r0 * Hh;
        float* o1 = o0 + 8 * Hh;
#pragma unroll
        for (int ni = 0; ni < 8; ni++) {
            const int col = bn + wn + ni * 8 + 2 * tig;
            float2 bv2 = *(const float2*)(bias + col);
            float2 w0, w1;
            w0.x = tf32r((acc[mi][ni][0] + bv2.x) * scale);
            w0.y = tf32r((acc[mi][ni][1] + bv2.y) * scale);
            w1.x = tf32r((acc[mi][ni][2] + bv2.x) * scale);
            w1.y = tf32r((acc[mi][ni][3] + bv2.y) * scale);
            *(float2*)(o0 + col) = w0;
            *(float2*)(o1 + col) = w1;
        }
    }
}

// scores = q @ k^T + attn_bias, masked -> attn buffer (pre-softmax fp32)
__global__ __launch_bounds__(256, 1) void scores_tc(const float* __restrict__ attn_bias,
                                                    const int* __restrict__ mask,
                                                    float* __restrict__ attn) {
    EPI_SETUP();
    const int b = blockIdx.z;
    float acc[4][8][4];
    gemm_loop(g_q + (size_t)b * Ss * Hh, g_k + (size_t)b * Ss * Hh,
              Hh, Hh, Hh, bm, bn, acc);

#pragma unroll
    for (int mi = 0; mi < 4; mi++) {
        const int r0 = bm + wm + mi * 16 + gid;
        const int r1 = r0 + 8;
        float* c0 = attn + ((size_t)b * Ss + r0) * Ss;
        float* c1 = attn + ((size_t)b * Ss + r1) * Ss;
        const float* ab0 = attn_bias + ((size_t)b * Ss + r0) * Ss;
        const float* ab1 = attn_bias + ((size_t)b * Ss + r1) * Ss;
        const int* m0 = mask + (size_t)r0 * Ss;
        const int* m1 = mask + (size_t)r1 * Ss;
#pragma unroll
        for (int ni = 0; ni < 8; ni++) {
            const int col = bn + wn + ni * 8 + 2 * tig;
            float2 b0 = *(const float2*)(ab0 + col);
            float2 b1 = *(const float2*)(ab1 + col);
            int2 k0 = *(const int2*)(m0 + col);
            int2 k1 = *(const int2*)(m1 + col);
            float2 w0, w1;
            w0.x = k0.x ? acc[mi][ni][0] + b0.x : NEGV;
            w0.y = k0.y ? acc[mi][ni][1] + b0.y : NEGV;
            w1.x = k1.x ? acc[mi][ni][2] + b1.x : NEGV;
            w1.y = k1.y ? acc[mi][ni][3] + b1.y : NEGV;
            *(float2*)(c0 + col) = w0;
            *(float2*)(c1 + col) = w1;
        }
    }
}

// ctx = round_tf32(attn @ vT^T)
__global__ __launch_bounds__(256, 1) void av_tc(const float* __restrict__ attn) {
    EPI_SETUP();
    const int b = blockIdx.z;
    float acc[4][8][4];
    gemm_loop(attn + (size_t)b * Ss * Ss, g_vt + (size_t)b * Hh * Ss,
              Ss, Ss, Ss, bm, bn, acc);

#pragma unroll
    for (int mi = 0; mi < 4; mi++) {
        const int r0 = bm + wm + mi * 16 + gid;
        float* o0 = g_ctx + ((size_t)b * Ss + r0) * Hh;
        float* o1 = o0 + 8 * Hh;
#pragma unroll
        for (int ni = 0; ni < 8; ni++) {
            const int col = bn + wn + ni * 8 + 2 * tig;
            float2 w0, w1;
            w0.x = tf32r(acc[mi][ni][0]);
            w0.y = tf32r(acc[mi][ni][1]);
            w1.x = tf32r(acc[mi][ni][2]);
            w1.y = tf32r(acc[mi][ni][3]);
            *(float2*)(o0 + col) = w0;
            *(float2*)(o1 + col) = w1;
        }
    }
}

// out = ctx @ Wa^T + ba + residual(x)
__global__ __launch_bounds__(256, 1) void proj_tc(const float* __restrict__ ba,
                                                  const float* __restrict__ x,
                                                  float* __restrict__ out) {
    EPI_SETUP();
    float acc[4][8][4];
    gemm_loop(g_ctx, g_wa, Hh, Hh, Hh, bm, bn, acc);

#pragma unroll
    for (int mi = 0; mi < 4; mi++) {
        const int r0 = bm + wm + mi * 16 + gid;
        float* o0 = out + (size_t)r0 * Hh;
        float* o1 = o0 + 8 * Hh;
        const float* x0 = x + (size_t)r0 * Hh;
        const float* x1 = x0 + 8 * Hh;
#pragma unroll
        for (int ni = 0; ni < 8; ni++) {
            const int col = bn + wn + ni * 8 + 2 * tig;
            float2 bv2 = *(const float2*)(ba + col);
            float2 r0v = *(const float2*)(x0 + col);
            float2 r1v = *(const float2*)(x1 + col);
            float2 w0, w1;
            w0.x = acc[mi][ni][0] + bv2.x + r0v.x;
            w0.y = acc[mi][ni][1] + bv2.y + r0v.y;
            w1.x = acc[mi][ni][2] + bv2.x + r1v.x;
            w1.y = acc[mi][ni][3] + bv2.y + r1v.y;
            *(float2*)(o0 + col) = w0;
            *(float2*)(o1 + col) = w1;
        }
    }
}

// ---------------- small kernels ----------------------------------------------------------

__global__ __launch_bounds__(256) void rcopy4(const float4* __restrict__ s,
                                              float4* __restrict__ d, int n) {
    int i = blockIdx.x * blockDim.x + threadIdx.x;
    if (i < n) {
        float4 v = s[i];
        v.x = tf32r(v.x); v.y = tf32r(v.y); v.z = tf32r(v.z); v.w = tf32r(v.w);
        d[i] = v;
    }
}

// vt[b][h][s] = v[b][s][h]
__global__ void vtrans_kernel() {
    __shared__ float t[32][33];
    const int b = blockIdx.z;
    const int s0 = blockIdx.x * 32, h0 = blockIdx.y * 32;
    const float* src = g_v + (size_t)b * Ss * Hh;
    float* dst = g_vt + (size_t)b * Hh * Ss;
    const int tx = threadIdx.x, ty = threadIdx.y;
#pragma unroll
    for (int i = 0; i < 32; i += 8)
        t[ty + i][tx] = src[(size_t)(s0 + ty + i) * Hh + h0 + tx];
    __syncthreads();
#pragma unroll
    for (int i = 0; i < 32; i += 8)
        dst[(size_t)(h0 + ty + i) * Ss + s0 + tx] = t[tx][ty + i];
}

__device__ __forceinline__ float warpMax(float v) {
#pragma unroll
    for (int o = 16; o; o >>= 1) v = fmaxf(v, __shfl_xor_sync(0xffffffffu, v, o));
    return v;
}
__device__ __forceinline__ float warpSum(float v) {
#pragma unroll
    for (int o = 16; o; o >>= 1) v += __shfl_xor_sync(0xffffffffu, v, o);
    return v;
}
__device__ __forceinline__ float blockMax(float v) {
    __shared__ float sh[8];
    v = warpMax(v);
    if ((threadIdx.x & 31) == 0) sh[threadIdx.x >> 5] = v;
    __syncthreads();
    float r = fmaxf(fmaxf(fmaxf(sh[0], sh[1]), fmaxf(sh[2], sh[3])),
                    fmaxf(fmaxf(sh[4], sh[5]), fmaxf(sh[6], sh[7])));
    __syncthreads();
    return r;
}
__device__ __forceinline__ float blockSum(float v) {
    __shared__ float sh[8];
    v = warpSum(v);
    if ((threadIdx.x & 31) == 0) sh[threadIdx.x >> 5] = v;
    __syncthreads();
    float r = sh[0] + sh[1] + sh[2] + sh[3] + sh[4] + sh[5] + sh[6] + sh[7];
    __syncthreads();
    return r;
}

// softmax over S=2048 (one 256-thread block per row); output rounded to tf32
__global__ __launch_bounds__(256) void softmax_kernel(float* __restrict__ attn) {
    size_t row = blockIdx.x;
    float4* p = (float4*)(attn + row * Ss);
    int tid = threadIdx.x;
    float4 v0 = p[tid];
    float4 v1 = p[tid + 256];
    float m = fmaxf(fmaxf(fmaxf(v0.x, v0.y), fmaxf(v0.z, v0.w)),
                    fmaxf(fmaxf(v1.x, v1.y), fmaxf(v1.z, v1.w)));
    m = blockMax(m);
    v0.x = __expf(v0.x - m); v0.y = __expf(v0.y - m);
    v0.z = __expf(v0.z - m); v0.w = __expf(v0.w - m);
    v1.x = __expf(v1.x - m); v1.y = __expf(v1.y - m);
    v1.z = __expf(v1.z - m); v1.w = __expf(v1.w - m);
    float s = v0.x + v0.y + v0.z + v0.w + v1.x + v1.y + v1.z + v1.w;
    s = blockSum(s);
    float inv = 1.0f / s;
    v0.x = tf32r(v0.x * inv); v0.y = tf32r(v0.y * inv);
    v0.z = tf32r(v0.z * inv); v0.w = tf32r(v0.w * inv);
    v1.x = tf32r(v1.x * inv); v1.y = tf32r(v1.y * inv);
    v1.z = tf32r(v1.z * inv); v1.w = tf32r(v1.w * inv);
    p[tid] = v0;
    p[tid + 256] = v1;
}

// in-place LayerNorm over H=1024 (biased variance, eps=1e-6)
__global__ __launch_bounds__(256) void ln_kernel(float* __restrict__ out,
                                                 const float* __restrict__ gamma,
                                                 const float* __restrict__ beta) {
    size_t row = blockIdx.x;
    float4* p = (float4*)(out + row * Hh);
    int tid = threadIdx.x;
    float4 v = p[tid];
    float s = v.x + v.y + v.z + v.w;
    s = blockSum(s);
    float mu = s * (1.0f / Hh);
    float dx = v.x - mu, dy = v.y - mu, dz = v.z - mu, dw = v.w - mu;
    float sq = dx * dx + dy * dy + dz * dz + dw * dw;
    sq = blockSum(sq);
    float rstd = rsqrtf(sq * (1.0f / Hh) + 1e-6f);
    float4 g = ((const float4*)gamma)[tid];
    float4 bt = ((const float4*)beta)[tid];
    v.x = dx * rstd * g.x + bt.x;
    v.y = dy * rstd * g.y + bt.y;
    v.z = dz * rstd * g.z + bt.z;
    v.w = dw * rstd * g.w + bt.w;
    p[tid] = v;
}

// ---------------- launch --------------------------------------------------------------
extern "C" void kernel_launch(void* const* d_in, const int* in_sizes, int n_in,
                              void* d_out, int out_size) {
    const float* x         = (const float*)d_in[0];
    const int*   mask      = (const int*)  d_in[1];
    const float* attn_bias = (const float*)d_in[2];
    const float* Wq = (const float*)d_in[3];  const float* bq = (const float*)d_in[4];
    const float* Wk = (const float*)d_in[5];  const float* bk = (const float*)d_in[6];
    const float* Wv = (const float*)d_in[7];  const float* bv = (const float*)d_in[8];
    const float* Wa = (const float*)d_in[9];  const float* ba = (const float*)d_in[10];
    const float* gamma = (const float*)d_in[11];
    const float* beta  = (const float*)d_in[12];

    float* out  = (float*)d_out;
    float* attn = out + (size_t)Bb * Ss * Hh;   // tuple (out, attn)

    void *p_xr, *p_wq, *p_wk, *p_wv, *p_wa;
    cudaGetSymbolAddress(&p_xr, g_xr);
    cudaGetSymbolAddress(&p_wq, g_wq);
    cudaGetSymbolAddress(&p_wk, g_wk);
    cudaGetSymbolAddress(&p_wv, g_wv);
    cudaGetSymbolAddress(&p_wa, g_wa);

    cudaFuncSetAttribute(qkv_tc,    cudaFuncAttributeMaxDynamicSharedMemorySize, DYN_SMEM);
    cudaFuncSetAttribute(scores_tc, cudaFuncAttributeMaxDynamicSharedMemorySize, DYN_SMEM);
    cudaFuncSetAttribute(av_tc,     cudaFuncAttributeMaxDynamicSharedMemorySize, DYN_SMEM);
    cudaFuncSetAttribute(proj_tc,   cudaFuncAttributeMaxDynamicSharedMemorySize, DYN_SMEM);

    // round operands to nearest-tf32 (kills HMMA input-truncation bias)
    int n4x = (Bb * Ss * Hh) / 4;
    int n4w = (Hh * Hh) / 4;
    rcopy4<<<(n4x + 255) / 256, 256>>>((const float4*)x,  (float4*)p_xr, n4x);
    rcopy4<<<(n4w + 255) / 256, 256>>>((const float4*)Wq, (float4*)p_wq, n4w);
    rcopy4<<<(n4w + 255) / 256, 256>>>((const float4*)Wk, (float4*)p_wk, n4w);
    rcopy4<<<(n4w + 255) / 256, 256>>>((const float4*)Wv, (float4*)p_wv, n4w);
    rcopy4<<<(n4w + 255) / 256, 256>>>((const float4*)Wa, (float4*)p_wa, n4w);

    qkv_tc<<<dim3(Hh / BN, (Bb * Ss) / BM, 3), 256, DYN_SMEM>>>(bq, bk, bv);
    vtrans_kernel<<<dim3(Ss / 32, Hh / 32, Bb), dim3(32, 8)>>>();
    scores_tc<<<dim3(Ss / BN, Ss / BM, Bb), 256, DYN_SMEM>>>(attn_bias, mask, attn);
    softmax_kernel<<<Bb * Ss, 256>>>(attn);
    av_tc<<<dim3(Hh / BN, Ss / BM, Bb), 256, DYN_SMEM>>>(attn);
    proj_tc<<<dim3(Hh / BN, (Bb * Ss) / BM), 256, DYN_SMEM>>>(ba, x, out);
    ln_kernel<<<Bb * Ss, 256>>>(out, gamma, beta);
}

// round 5
// speedup vs baseline: 2.2470x; 1.0002x over previous
#include <cuda_runtime.h>
#include <cstdint>
#include <math.h>

#define Bb 8
#define Ss 2048
#define Hh 1024
#define NEGV (-1e12f)

// ---------------- mma.sync tf32 GEMM configuration -----------------------------------
constexpr int BM = 128, BN = 256, BKT = 32;        // CTA tile
constexpr int ROWB = 36 * 4;                       // smem row pitch: 32 floats + 4 pad = 144B
constexpr int ABYTES = BM * ROWB;                  // 18432
constexpr int BBYTES = BN * ROWB;                  // 36864
constexpr int STAGE  = ABYTES + BBYTES;            // 55296
constexpr int NSTG   = 3;
constexpr int DYN_SMEM = NSTG * STAGE;             // 165888

// ---------------- scratch (static device memory) -------------------------------------
__device__ float g_xr [(size_t)Bb * Ss * Hh];
__device__ float g_q  [(size_t)Bb * Ss * Hh];
__device__ float g_k  [(size_t)Bb * Ss * Hh];
__device__ float g_v  [(size_t)Bb * Ss * Hh];
__device__ float g_vt [(size_t)Bb * Ss * Hh];
__device__ float g_ctx[(size_t)Bb * Ss * Hh];
__device__ float g_wq[Hh * Hh], g_wk[Hh * Hh], g_wv[Hh * Hh], g_wa[Hh * Hh];

// ---------------- helpers --------------------------------------------------------------
__device__ __forceinline__ uint32_t smem_u32(const void* p) {
    uint32_t a;
    asm("{ .reg .u64 t; cvta.to.shared.u64 t, %1; cvt.u32.u64 %0, t; }" : "=r"(a) : "l"(p));
    return a;
}
__device__ __forceinline__ float tf32r(float x) {
    uint32_t u;
    asm("cvt.rna.tf32.f32 %0, %1;" : "=r"(u) : "f"(x));
    return __uint_as_float(u);
}
__device__ __forceinline__ void cpa(uint32_t dst, const float* src) {
    asm volatile("cp.async.cg.shared.global [%0], [%1], 16;" :: "r"(dst), "l"(src));
}
__device__ __forceinline__ void cpa_commit() { asm volatile("cp.async.commit_group;"); }
template <int N>
__device__ __forceinline__ void cpa_wait() { asm volatile("cp.async.wait_group %0;" :: "n"(N)); }

__device__ __forceinline__ void mma8(float d[4], const uint32_t a[4], const uint32_t b[2]) {
    asm volatile(
        "mma.sync.aligned.m16n8k8.row.col.f32.tf32.tf32.f32 "
        "{%0,%1,%2,%3}, {%4,%5,%6,%7}, {%8,%9}, {%0,%1,%2,%3};"
        : "+f"(d[0]), "+f"(d[1]), "+f"(d[2]), "+f"(d[3])
        : "r"(a[0]), "r"(a[1]), "r"(a[2]), "r"(a[3]), "r"(b[0]), "r"(b[1]));
}

// ---------------- GEMM mainloop: acc[4][8][4] = A[bm:bm+128] * B[bn:bn+256]^T ---------
// A: [M,K] row-major, B: [N,K] row-major (i.e. computes A @ B^T)
__device__ __forceinline__ void gemm_loop(const float* __restrict__ A,
                                          const float* __restrict__ B,
                                          int K, int lda, int ldb, int bm, int bn,
                                          float acc[4][8][4]) {
    extern __shared__ __align__(16) char dsm[];
    const int tid = threadIdx.x;
    const int wid = tid >> 5, lane = tid & 31;
    const int gid = lane >> 2, tig = lane & 3;
    const int wm = (wid & 1) * 64, wn = (wid >> 1) * 64;
    const int NK = K / BKT;

#pragma unroll
    for (int mi = 0; mi < 4; mi++)
#pragma unroll
        for (int ni = 0; ni < 8; ni++)
#pragma unroll
            for (int j = 0; j < 4; j++) acc[mi][ni][j] = 0.0f;

    const int ar = tid >> 1, ac = (tid & 1) * 16;   // A: row ar, float offset ac
    const uint32_t sbase = smem_u32(dsm);

    auto load_tile = [&](int s, int kt) {
        uint32_t sA = sbase + s * STAGE;
        uint32_t sB = sA + ABYTES;
        const float* asrc = A + (size_t)(bm + ar) * lda + kt * BKT + ac;
        uint32_t ad = sA + ar * ROWB + ac * 4;
#pragma unroll
        for (int c = 0; c < 4; c++) cpa(ad + c * 16, asrc + c * 4);
        const float* bsrc = B + (size_t)(bn + tid) * ldb + kt * BKT;
        uint32_t bd = sB + tid * ROWB;
#pragma unroll
        for (int c = 0; c < 8; c++) cpa(bd + c * 16, bsrc + c * 4);
    };

    load_tile(0, 0); cpa_commit();
    load_tile(1, 1); cpa_commit();

    for (int kt = 0; kt < NK; kt++) {
        const int s = kt % NSTG;
        if (kt + 1 < NK) cpa_wait<1>(); else cpa_wait<0>();
        __syncthreads();
        if (kt + 2 < NK) { load_tile((kt + 2) % NSTG, kt + 2); cpa_commit(); }

        const float* As = (const float*)(dsm + s * STAGE);
        const float* Bs = (const float*)(dsm + s * STAGE + ABYTES);
#pragma unroll
        for (int kk = 0; kk < 4; kk++) {
            uint32_t a[4][4], b[8][2];
#pragma unroll
            for (int mi = 0; mi < 4; mi++) {
                const float* p0 = As + (wm + mi * 16 + gid) * 36 + kk * 8 + tig;
                const float* p1 = p0 + 8 * 36;
                a[mi][0] = __float_as_uint(p0[0]);
                a[mi][1] = __float_as_uint(p1[0]);
                a[mi][2] = __float_as_uint(p0[4]);
                a[mi][3] = __float_as_uint(p1[4]);
            }
#pragma unroll
            for (int ni = 0; ni < 8; ni++) {
                const float* p = Bs + (wn + ni * 8 + gid) * 36 + kk * 8 + tig;
                b[ni][0] = __float_as_uint(p[0]);
                b[ni][1] = __float_as_uint(p[4]);
            }
#pragma unroll
            for (int mi = 0; mi < 4; mi++)
#pragma unroll
                for (int ni = 0; ni < 8; ni++)
                    mma8(acc[mi][ni], a[mi], b[ni]);
        }
        // next-iteration top barrier provides the reuse fence
    }
}

// fragment -> global coordinates helper values
#define EPI_SETUP()                                        \
    const int tid = threadIdx.x;                           \
    const int wid = tid >> 5, lane = tid & 31;             \
    const int gid = lane >> 2, tig = lane & 3;             \
    const int wm = (wid & 1) * 64, wn = (wid >> 1) * 64;   \
    const int bm = blockIdx.y * BM, bn = blockIdx.x * BN;  \
    (void)bm; (void)bn;

// ---------------- GEMM kernels ---------------------------------------------------------

// q/k/v = round_tf32((x_r @ W^T + b) * scale);  q folds 1/(T*sqrt(H)) = 1/32
__global__ __launch_bounds__(256, 1) void qkv_tc(const float* __restrict__ bq,
                                                 const float* __restrict__ bk,
                                                 const float* __restrict__ bv) {
    EPI_SETUP();
    const float* W; const float* bias; float* out; float scale;
    if (blockIdx.z == 0)      { W = g_wq; bias = bq; out = g_q; scale = 1.0f / 32.0f; }
    else if (blockIdx.z == 1) { W = g_wk; bias = bk; out = g_k; scale = 1.0f; }
    else                      { W = g_wv; bias = bv; out = g_v; scale = 1.0f; }

    float acc[4][8][4];
    gemm_loop(g_xr, W, Hh, Hh, Hh, bm, bn, acc);

#pragma unroll
    for (int mi = 0; mi < 4; mi++) {
        const int r0 = bm + wm + mi * 16 + gid;
        float* o0 = out + (size_t)r0 * Hh;
        float* o1 = o0 + 8 * Hh;
#pragma unroll
        for (int ni = 0; ni < 8; ni++) {
            const int col = bn + wn + ni * 8 + 2 * tig;
            float2 bv2 = *(const float2*)(bias + col);
            float2 w0, w1;
            w0.x = tf32r((acc[mi][ni][0] + bv2.x) * scale);
            w0.y = tf32r((acc[mi][ni][1] + bv2.y) * scale);
            w1.x = tf32r((acc[mi][ni][2] + bv2.x) * scale);
            w1.y = tf32r((acc[mi][ni][3] + bv2.y) * scale);
            *(float2*)(o0 + col) = w0;
            *(float2*)(o1 + col) = w1;
        }
    }
}

// scores = q @ k^T + attn_bias, masked -> attn buffer (pre-softmax fp32)
__global__ __launch_bounds__(256, 1) void scores_tc(const float* __restrict__ attn_bias,
                                                    const int* __restrict__ mask,
                                                    float* __restrict__ attn) {
    EPI_SETUP();
    const int b = blockIdx.z;
    float acc[4][8][4];
    gemm_loop(g_q + (size_t)b * Ss * Hh, g_k + (size_t)b * Ss * Hh,
              Hh, Hh, Hh, bm, bn, acc);

#pragma unroll
    for (int mi = 0; mi < 4; mi++) {
        const int r0 = bm + wm + mi * 16 + gid;
        const int r1 = r0 + 8;
        float* c0 = attn + ((size_t)b * Ss + r0) * Ss;
        float* c1 = attn + ((size_t)b * Ss + r1) * Ss;
        const float* ab0 = attn_bias + ((size_t)b * Ss + r0) * Ss;
        const float* ab1 = attn_bias + ((size_t)b * Ss + r1) * Ss;
        const int* m0 = mask + (size_t)r0 * Ss;
        const int* m1 = mask + (size_t)r1 * Ss;
#pragma unroll
        for (int ni = 0; ni < 8; ni++) {
            const int col = bn + wn + ni * 8 + 2 * tig;
            float2 b0 = *(const float2*)(ab0 + col);
            float2 b1 = *(const float2*)(ab1 + col);
            int2 k0 = *(const int2*)(m0 + col);
            int2 k1 = *(const int2*)(m1 + col);
            float2 w0, w1;
            w0.x = k0.x ? acc[mi][ni][0] + b0.x : NEGV;
            w0.y = k0.y ? acc[mi][ni][1] + b0.y : NEGV;
            w1.x = k1.x ? acc[mi][ni][2] + b1.x : NEGV;
            w1.y = k1.y ? acc[mi][ni][3] + b1.y : NEGV;
            *(float2*)(c0 + col) = w0;
            *(float2*)(c1 + col) = w1;
        }
    }
}

// ctx = round_tf32(attn @ vT^T)
__global__ __launch_bounds__(256, 1) void av_tc(const float* __restrict__ attn) {
    EPI_SETUP();
    const int b = blockIdx.z;
    float acc[4][8][4];
    gemm_loop(attn + (size_t)b * Ss * Ss, g_vt + (size_t)b * Hh * Ss,
              Ss, Ss, Ss, bm, bn, acc);

#pragma unroll
    for (int mi = 0; mi < 4; mi++) {
        const int r0 = bm + wm + mi * 16 + gid;
        float* o0 = g_ctx + ((size_t)b * Ss + r0) * Hh;
        float* o1 = o0 + 8 * Hh;
#pragma unroll
        for (int ni = 0; ni < 8; ni++) {
            const int col = bn + wn + ni * 8 + 2 * tig;
            float2 w0, w1;
            w0.x = tf32r(acc[mi][ni][0]);
            w0.y = tf32r(acc[mi][ni][1]);
            w1.x = tf32r(acc[mi][ni][2]);
            w1.y = tf32r(acc[mi][ni][3]);
            *(float2*)(o0 + col) = w0;
            *(float2*)(o1 + col) = w1;
        }
    }
}

// out = ctx @ Wa^T + ba + residual(x)
__global__ __launch_bounds__(256, 1) void proj_tc(const float* __restrict__ ba,
                                                  const float* __restrict__ x,
                                                  float* __restrict__ out) {
    EPI_SETUP();
    float acc[4][8][4];
    gemm_loop(g_ctx, g_wa, Hh, Hh, Hh, bm, bn, acc);

#pragma unroll
    for (int mi = 0; mi < 4; mi++) {
        const int r0 = bm + wm + mi * 16 + gid;
        float* o0 = out + (size_t)r0 * Hh;
        float* o1 = o0 + 8 * Hh;
        const float* x0 = x + (size_t)r0 * Hh;
        const float* x1 = x0 + 8 * Hh;
#pragma unroll
        for (int ni = 0; ni < 8; ni++) {
            const int col = bn + wn + ni * 8 + 2 * tig;
            float2 bv2 = *(const float2*)(ba + col);
            float2 r0v = *(const float2*)(x0 + col);
            float2 r1v = *(const float2*)(x1 + col);
            float2 w0, w1;
            w0.x = acc[mi][ni][0] + bv2.x + r0v.x;
            w0.y = acc[mi][ni][1] + bv2.y + r0v.y;
            w1.x = acc[mi][ni][2] + bv2.x + r1v.x;
            w1.y = acc[mi][ni][3] + bv2.y + r1v.y;
            *(float2*)(o0 + col) = w0;
            *(float2*)(o1 + col) = w1;
        }
    }
}

// ---------------- small kernels ----------------------------------------------------------

__global__ __launch_bounds__(256) void rcopy4(const float4* __restrict__ s,
                                              float4* __restrict__ d, int n) {
    int i = blockIdx.x * blockDim.x + threadIdx.x;
    if (i < n) {
        float4 v = s[i];
        v.x = tf32r(v.x); v.y = tf32r(v.y); v.z = tf32r(v.z); v.w = tf32r(v.w);
        d[i] = v;
    }
}

// vt[b][h][s] = v[b][s][h]
__global__ void vtrans_kernel() {
    __shared__ float t[32][33];
    const int b = blockIdx.z;
    const int s0 = blockIdx.x * 32, h0 = blockIdx.y * 32;
    const float* src = g_v + (size_t)b * Ss * Hh;
    float* dst = g_vt + (size_t)b * Hh * Ss;
    const int tx = threadIdx.x, ty = threadIdx.y;
#pragma unroll
    for (int i = 0; i < 32; i += 8)
        t[ty + i][tx] = src[(size_t)(s0 + ty + i) * Hh + h0 + tx];
    __syncthreads();
#pragma unroll
    for (int i = 0; i < 32; i += 8)
        dst[(size_t)(h0 + ty + i) * Ss + s0 + tx] = t[tx][ty + i];
}

__device__ __forceinline__ float warpMax(float v) {
#pragma unroll
    for (int o = 16; o; o >>= 1) v = fmaxf(v, __shfl_xor_sync(0xffffffffu, v, o));
    return v;
}
__device__ __forceinline__ float warpSum(float v) {
#pragma unroll
    for (int o = 16; o; o >>= 1) v += __shfl_xor_sync(0xffffffffu, v, o);
    return v;
}
__device__ __forceinline__ float blockMax(float v) {
    __shared__ float sh[8];
    v = warpMax(v);
    if ((threadIdx.x & 31) == 0) sh[threadIdx.x >> 5] = v;
    __syncthreads();
    float r = fmaxf(fmaxf(fmaxf(sh[0], sh[1]), fmaxf(sh[2], sh[3])),
                    fmaxf(fmaxf(sh[4], sh[5]), fmaxf(sh[6], sh[7])));
    __syncthreads();
    return r;
}
__device__ __forceinline__ float blockSum(float v) {
    __shared__ float sh[8];
    v = warpSum(v);
    if ((threadIdx.x & 31) == 0) sh[threadIdx.x >> 5] = v;
    __syncthreads();
    float r = sh[0] + sh[1] + sh[2] + sh[3] + sh[4] + sh[5] + sh[6] + sh[7];
    __syncthreads();
    return r;
}

// softmax over S=2048 (one 256-thread block per row); output rounded to tf32
__global__ __launch_bounds__(256) void softmax_kernel(float* __restrict__ attn) {
    size_t row = blockIdx.x;
    float4* p = (float4*)(attn + row * Ss);
    int tid = threadIdx.x;
    float4 v0 = p[tid];
    float4 v1 = p[tid + 256];
    float m = fmaxf(fmaxf(fmaxf(v0.x, v0.y), fmaxf(v0.z, v0.w)),
                    fmaxf(fmaxf(v1.x, v1.y), fmaxf(v1.z, v1.w)));
    m = blockMax(m);
    v0.x = __expf(v0.x - m); v0.y = __expf(v0.y - m);
    v0.z = __expf(v0.z - m); v0.w = __expf(v0.w - m);
    v1.x = __expf(v1.x - m); v1.y = __expf(v1.y - m);
    v1.z = __expf(v1.z - m); v1.w = __expf(v1.w - m);
    float s = v0.x + v0.y + v0.z + v0.w + v1.x + v1.y + v1.z + v1.w;
    s = blockSum(s);
    float inv = 1.0f / s;
    v0.x = tf32r(v0.x * inv); v0.y = tf32r(v0.y * inv);
    v0.z = tf32r(v0.z * inv); v0.w = tf32r(v0.w * inv);
    v1.x = tf32r(v1.x * inv); v1.y = tf32r(v1.y * inv);
    v1.z = tf32r(v1.z * inv); v1.w = tf32r(v1.w * inv);
    p[tid] = v0;
    p[tid + 256] = v1;
}

// in-place LayerNorm over H=1024 (biased variance, eps=1e-6)
__global__ __launch_bounds__(256) void ln_kernel(float* __restrict__ out,
                                                 const float* __restrict__ gamma,
                                                 const float* __restrict__ beta) {
    size_t row = blockIdx.x;
    float4* p = (float4*)(out + row * Hh);
    int tid = threadIdx.x;
    float4 v = p[tid];
    float s = v.x + v.y + v.z + v.w;
    s = blockSum(s);
    float mu = s * (1.0f / Hh);
    float dx = v.x - mu, dy = v.y - mu, dz = v.z - mu, dw = v.w - mu;
    float sq = dx * dx + dy * dy + dz * dz + dw * dw;
    sq = blockSum(sq);
    float rstd = rsqrtf(sq * (1.0f / Hh) + 1e-6f);
    float4 g = ((const float4*)gamma)[tid];
    float4 bt = ((const float4*)beta)[tid];
    v.x = dx * rstd * g.x + bt.x;
    v.y = dy * rstd * g.y + bt.y;
    v.z = dz * rstd * g.z + bt.z;
    v.w = dw * rstd * g.w + bt.w;
    p[tid] = v;
}

// ---------------- launch --------------------------------------------------------------
extern "C" void kernel_launch(void* const* d_in, const int* in_sizes, int n_in,
                              void* d_out, int out_size) {
    const float* x         = (const float*)d_in[0];
    const int*   mask      = (const int*)  d_in[1];
    const float* attn_bias = (const float*)d_in[2];
    const float* Wq = (const float*)d_in[3];  const float* bq = (const float*)d_in[4];
    const float* Wk = (const float*)d_in[5];  const float* bk = (const float*)d_in[6];
    const float* Wv = (const float*)d_in[7];  const float* bv = (const float*)d_in[8];
    const float* Wa = (const float*)d_in[9];  const float* ba = (const float*)d_in[10];
    const float* gamma = (const float*)d_in[11];
    const float* beta  = (const float*)d_in[12];

    float* out  = (float*)d_out;
    float* attn = out + (size_t)Bb * Ss * Hh;   // tuple (out, attn)

    void *p_xr, *p_wq, *p_wk, *p_wv, *p_wa;
    cudaGetSymbolAddress(&p_xr, g_xr);
    cudaGetSymbolAddress(&p_wq, g_wq);
    cudaGetSymbolAddress(&p_wk, g_wk);
    cudaGetSymbolAddress(&p_wv, g_wv);
    cudaGetSymbolAddress(&p_wa, g_wa);

    cudaFuncSetAttribute(qkv_tc,    cudaFuncAttributeMaxDynamicSharedMemorySize, DYN_SMEM);
    cudaFuncSetAttribute(scores_tc, cudaFuncAttributeMaxDynamicSharedMemorySize, DYN_SMEM);
    cudaFuncSetAttribute(av_tc,     cudaFuncAttributeMaxDynamicSharedMemorySize, DYN_SMEM);
    cudaFuncSetAttribute(proj_tc,   cudaFuncAttributeMaxDynamicSharedMemorySize, DYN_SMEM);

    // round operands to nearest-tf32 (kills HMMA input-truncation bias)
    int n4x = (Bb * Ss * Hh) / 4;
    int n4w = (Hh * Hh) / 4;
    rcopy4<<<(n4x + 255) / 256, 256>>>((const float4*)x,  (float4*)p_xr, n4x);
    rcopy4<<<(n4w + 255) / 256, 256>>>((const float4*)Wq, (float4*)p_wq, n4w);
    rcopy4<<<(n4w + 255) / 256, 256>>>((const float4*)Wk, (float4*)p_wk, n4w);
    rcopy4<<<(n4w + 255) / 256, 256>>>((const float4*)Wv, (float4*)p_wv, n4w);
    rcopy4<<<(n4w + 255) / 256, 256>>>((const float4*)Wa, (float4*)p_wa, n4w);

    qkv_tc<<<dim3(Hh / BN, (Bb * Ss) / BM, 3), 256, DYN_SMEM>>>(bq, bk, bv);
    vtrans_kernel<<<dim3(Ss / 32, Hh / 32, Bb), dim3(32, 8)>>>();
    scores_tc<<<dim3(Ss / BN, Ss / BM, Bb), 256, DYN_SMEM>>>(attn_bias, mask, attn);
    softmax_kernel<<<Bb * Ss, 256>>>(attn);
    av_tc<<<dim3(Hh / BN, Ss / BM, Bb), 256, DYN_SMEM>>>(attn);
    proj_tc<<<dim3(Hh / BN, (Bb * Ss) / BM), 256, DYN_SMEM>>>(ba, x, out);
    ln_kernel<<<Bb * Ss, 256>>>(out, gamma, beta);
}